// round 3
// baseline (speedup 1.0000x reference)
#include <cuda_runtime.h>
#include <math.h>

#define N_NODES 50000
#define N_EDGES 800000
#define EMB     100
#define NF4     25          // float4 per row

// ---- static scratch (allocation-free rule: __device__ globals) ----
__device__ int   g_rowoff[N_NODES + 1];   // CSR row offsets
__device__ int   g_cursor[N_NODES];       // counts -> scatter cursors
__device__ int2  g_edges[N_EDGES];        // packed {col*EMB, val bits}, grouped by row
__device__ float g_x1[N_NODES * EMB];
__device__ float g_x2[N_NODES * EMB];

// ---------------- CSR build ----------------
__global__ void hist_kernel(const int* __restrict__ row) {
    int e = blockIdx.x * blockDim.x + threadIdx.x;
    if (e < N_EDGES) atomicAdd(&g_cursor[row[e]], 1);
}

// single-block two-pass scan: counts (g_cursor) -> rowoff (inclusive at i+1)
// and cursor <- exclusive start offsets.
__global__ void __launch_bounds__(1024) scan_kernel() {
    const int C = (N_NODES + 1023) / 1024;      // 49
    const int t = threadIdx.x;
    const int s = t * C;
    const int e = min(s + C, N_NODES);

    // pass 1: per-thread chunk sum
    int sum = 0;
    for (int i = s; i < e; i++) sum += g_cursor[i];

    // exclusive block scan of the 1024 sums
    __shared__ int wsum[32];
    const int lane = t & 31, warp = t >> 5;
    int x = sum;
    #pragma unroll
    for (int off = 1; off < 32; off <<= 1) {
        int y = __shfl_up_sync(0xFFFFFFFFu, x, off);
        if (lane >= off) x += y;
    }
    if (lane == 31) wsum[warp] = x;
    __syncthreads();
    if (warp == 0) {
        int w = wsum[lane];
        #pragma unroll
        for (int off = 1; off < 32; off <<= 1) {
            int y = __shfl_up_sync(0xFFFFFFFFu, w, off);
            if (lane >= off) w += y;
        }
        wsum[lane] = w;
    }
    __syncthreads();
    int base = x - sum + (warp > 0 ? wsum[warp - 1] : 0);   // exclusive prefix

    // pass 2: rewrite with running prefix
    if (t == 0) g_rowoff[0] = 0;
    int run = base;
    for (int i = s; i < e; i++) {
        int v = g_cursor[i];
        g_cursor[i] = run;            // exclusive start (scatter cursor)
        run += v;
        g_rowoff[i + 1] = run;        // inclusive
    }
}

__global__ void scatter_kernel(const int* __restrict__ row,
                               const int* __restrict__ col,
                               const float* __restrict__ val) {
    int e = blockIdx.x * blockDim.x + threadIdx.x;
    if (e < N_EDGES) {
        int pos = atomicAdd(&g_cursor[row[e]], 1);
        g_edges[pos] = make_int2(col[e] * EMB, __float_as_int(val[e]));
    }
}

// ---------------- SpMM: warp per row, float4 gathers ----------------
__device__ __forceinline__ float4 spmm_row(const float* __restrict__ x,
                                           int r, int lane) {
    const int s = g_rowoff[r];
    const int e = g_rowoff[r + 1];
    float4 acc = make_float4(0.f, 0.f, 0.f, 0.f);
    for (int base = s; base < e; base += 32) {
        const int n = min(32, e - base);
        int2 ed = (base + lane < e) ? g_edges[base + lane] : make_int2(0, 0);
        for (int k = 0; k < n; k++) {
            const int   c = __shfl_sync(0xFFFFFFFFu, ed.x, k);
            const float v = __int_as_float(__shfl_sync(0xFFFFFFFFu, ed.y, k));
            if (lane < NF4) {
                float4 xv = __ldg((const float4*)(x + c) + lane);
                acc.x += v * xv.x;
                acc.y += v * xv.y;
                acc.z += v * xv.z;
                acc.w += v * xv.w;
            }
        }
    }
    return acc;
}

__global__ void __launch_bounds__(256) spmm_kernel(
    const float* __restrict__ x, float* __restrict__ y) {
    const int r = (blockIdx.x * blockDim.x + threadIdx.x) >> 5;
    if (r >= N_NODES) return;
    const int lane = threadIdx.x & 31;
    float4 acc = spmm_row(x, r, lane);
    if (lane < NF4)
        ((float4*)(y + (size_t)r * EMB))[lane] = acc;
}

// ---------------- layer-3 SpMM fused with normalize + weighted sum ----------------
__device__ __forceinline__ float dot4(float4 p) {
    return p.x * p.x + p.y * p.y + p.z * p.z + p.w * p.w;
}

__global__ void __launch_bounds__(256) spmm_final_kernel(
    const float* __restrict__ x2in, const float* __restrict__ emb,
    const float* __restrict__ a, float* __restrict__ out) {
    const int r = (blockIdx.x * blockDim.x + threadIdx.x) >> 5;
    if (r >= N_NODES) return;
    const int lane = threadIdx.x & 31;

    float4 v3 = spmm_row(x2in, r, lane);   // layer 3 row, in registers

    const float4 zero = make_float4(0.f, 0.f, 0.f, 0.f);
    float4 v0 = zero, v1 = zero, v2 = zero;
    if (lane < NF4) {
        v0 = __ldg((const float4*)(emb  + (size_t)r * EMB) + lane);
        v1 = __ldg((const float4*)(g_x1 + (size_t)r * EMB) + lane);
        v2 = __ldg((const float4*)(g_x2 + (size_t)r * EMB) + lane);
    }

    float sq[4];
    sq[0] = dot4(v0); sq[1] = dot4(v1); sq[2] = dot4(v2);
    sq[3] = (lane < NF4) ? dot4(v3) : 0.0f;

    #pragma unroll
    for (int off = 16; off > 0; off >>= 1) {
        #pragma unroll
        for (int l = 0; l < 4; l++)
            sq[l] += __shfl_xor_sync(0xFFFFFFFFu, sq[l], off);
    }

    if (lane < NF4) {
        float w0 = __ldg(&a[0]) / fmaxf(sqrtf(sq[0]), 1e-12f);
        float w1 = __ldg(&a[1]) / fmaxf(sqrtf(sq[1]), 1e-12f);
        float w2 = __ldg(&a[2]) / fmaxf(sqrtf(sq[2]), 1e-12f);
        float w3 = __ldg(&a[3]) / fmaxf(sqrtf(sq[3]), 1e-12f);
        float4 res;
        res.x = w0 * v0.x + w1 * v1.x + w2 * v2.x + w3 * v3.x;
        res.y = w0 * v0.y + w1 * v1.y + w2 * v2.y + w3 * v3.y;
        res.z = w0 * v0.z + w1 * v1.z + w2 * v2.z + w3 * v3.z;
        res.w = w0 * v0.w + w1 * v1.w + w2 * v2.w + w3 * v3.w;
        ((float4*)(out + (size_t)r * EMB))[lane] = res;
    }
}

extern "C" void kernel_launch(void* const* d_in, const int* in_sizes, int n_in,
                              void* d_out, int out_size) {
    const int*   adj_row = (const int*)d_in[0];
    const int*   adj_col = (const int*)d_in[1];
    const float* adj_val = (const float*)d_in[2];
    const float* emb     = (const float*)d_in[3];
    const float* a       = (const float*)d_in[4];
    float*       out     = (float*)d_out;

    float* x1;  cudaGetSymbolAddress((void**)&x1, g_x1);
    float* x2;  cudaGetSymbolAddress((void**)&x2, g_x2);
    int*   cur; cudaGetSymbolAddress((void**)&cur, g_cursor);

    // CSR build
    cudaMemsetAsync(cur, 0, N_NODES * sizeof(int), 0);
    hist_kernel<<<(N_EDGES + 255) / 256, 256>>>(adj_row);
    scan_kernel<<<1, 1024>>>();
    scatter_kernel<<<(N_EDGES + 255) / 256, 256>>>(adj_row, adj_col, adj_val);

    // SpMM layers (warp per row); layer 3 fused with normalize+sum
    const int SPMM_BLOCKS = (N_NODES * 32 + 255) / 256;
    spmm_kernel<<<SPMM_BLOCKS, 256>>>(emb, x1);
    spmm_kernel<<<SPMM_BLOCKS, 256>>>(x1,  x2);
    spmm_final_kernel<<<SPMM_BLOCKS, 256>>>(x2, emb, a, out);
}

// round 4
// speedup vs baseline: 1.5490x; 1.5490x over previous
#include <cuda_runtime.h>
#include <math.h>

#define N_NODES 50000
#define N_EDGES 800000
#define EMB     100
#define NF4     25          // float4 per row
#define SCAN_B  256
#define SCAN_NB ((N_NODES + SCAN_B - 1) / SCAN_B)   // 196

// ---- static scratch (allocation-free rule: __device__ globals) ----
__device__ int   g_rowoff[N_NODES + 1];   // CSR row offsets
__device__ int   g_cursor[N_NODES];       // counts -> scatter cursors
__device__ int   g_bsum[SCAN_NB];         // per-block scan sums
__device__ int2  g_edges[N_EDGES];        // packed {col*EMB, val bits}, grouped by row
__device__ float g_x1[N_NODES * EMB];
__device__ float g_x2[N_NODES * EMB];

// ---------------- CSR build ----------------
__global__ void hist_kernel(const int* __restrict__ row) {
    int e = blockIdx.x * blockDim.x + threadIdx.x;
    if (e < N_EDGES) atomicAdd(&g_cursor[row[e]], 1);
}

// per-block inclusive scan of counts -> g_rowoff[i+1] (local), block sum -> g_bsum
__global__ void block_scan_kernel() {
    __shared__ int wsum[8];
    int i = blockIdx.x * SCAN_B + threadIdx.x;
    int lane = threadIdx.x & 31, warp = threadIdx.x >> 5;
    int v = (i < N_NODES) ? g_cursor[i] : 0;
    int x = v;
    #pragma unroll
    for (int off = 1; off < 32; off <<= 1) {
        int y = __shfl_up_sync(0xFFFFFFFFu, x, off);
        if (lane >= off) x += y;
    }
    if (lane == 31) wsum[warp] = x;
    __syncthreads();
    if (warp == 0) {
        int w = (lane < 8) ? wsum[lane] : 0;
        #pragma unroll
        for (int off = 1; off < 8; off <<= 1) {
            int y = __shfl_up_sync(0xFFFFFFFFu, w, off);
            if (lane >= off) w += y;
        }
        if (lane < 8) wsum[lane] = w;
    }
    __syncthreads();
    int incl = x + (warp > 0 ? wsum[warp - 1] : 0);
    if (i < N_NODES) g_rowoff[i + 1] = incl;
    if (threadIdx.x == SCAN_B - 1) g_bsum[blockIdx.x] = incl;
}

// single-block scan of the 196 block sums (exclusive, in place)
__global__ void bsum_scan_kernel() {
    __shared__ int wsum[8];
    int t = threadIdx.x;                 // 256 threads
    int lane = t & 31, warp = t >> 5;
    int v = (t < SCAN_NB) ? g_bsum[t] : 0;
    int x = v;
    #pragma unroll
    for (int off = 1; off < 32; off <<= 1) {
        int y = __shfl_up_sync(0xFFFFFFFFu, x, off);
        if (lane >= off) x += y;
    }
    if (lane == 31) wsum[warp] = x;
    __syncthreads();
    if (warp == 0) {
        int w = (lane < 8) ? wsum[lane] : 0;
        #pragma unroll
        for (int off = 1; off < 8; off <<= 1) {
            int y = __shfl_up_sync(0xFFFFFFFFu, w, off);
            if (lane >= off) w += y;
        }
        if (lane < 8) wsum[lane] = w;
    }
    __syncthreads();
    int excl = x - v + (warp > 0 ? wsum[warp - 1] : 0);
    if (t < SCAN_NB) g_bsum[t] = excl;
}

// add block offsets; produce final rowoff and cursors (counts still in g_cursor)
__global__ void fixup_kernel() {
    int i = blockIdx.x * SCAN_B + threadIdx.x;
    if (i < N_NODES) {
        int incl = g_rowoff[i + 1] + g_bsum[blockIdx.x];
        g_rowoff[i + 1] = incl;
        g_cursor[i] = incl - g_cursor[i];   // exclusive start = cursor
        if (i == 0) g_rowoff[0] = 0;
    }
}

__global__ void scatter_kernel(const int* __restrict__ row,
                               const int* __restrict__ col,
                               const float* __restrict__ val) {
    int e = blockIdx.x * blockDim.x + threadIdx.x;
    if (e < N_EDGES) {
        int pos = atomicAdd(&g_cursor[row[e]], 1);
        g_edges[pos] = make_int2(col[e] * EMB, __float_as_int(val[e]));
    }
}

// ---------------- SpMM: warp per row, float4 gathers ----------------
__device__ __forceinline__ float4 spmm_row(const float* __restrict__ x,
                                           int r, int lane) {
    const int s = g_rowoff[r];
    const int e = g_rowoff[r + 1];
    float4 acc = make_float4(0.f, 0.f, 0.f, 0.f);
    for (int base = s; base < e; base += 32) {
        const int n = min(32, e - base);
        int2 ed = (base + lane < e) ? g_edges[base + lane] : make_int2(0, 0);
        for (int k = 0; k < n; k++) {
            const int   c = __shfl_sync(0xFFFFFFFFu, ed.x, k);
            const float v = __int_as_float(__shfl_sync(0xFFFFFFFFu, ed.y, k));
            if (lane < NF4) {
                float4 xv = __ldg((const float4*)(x + c) + lane);
                acc.x += v * xv.x;
                acc.y += v * xv.y;
                acc.z += v * xv.z;
                acc.w += v * xv.w;
            }
        }
    }
    return acc;
}

__global__ void __launch_bounds__(256) spmm_kernel(
    const float* __restrict__ x, float* __restrict__ y) {
    const int r = (blockIdx.x * blockDim.x + threadIdx.x) >> 5;
    if (r >= N_NODES) return;
    const int lane = threadIdx.x & 31;
    float4 acc = spmm_row(x, r, lane);
    if (lane < NF4)
        ((float4*)(y + (size_t)r * EMB))[lane] = acc;
}

// ---------------- layer-3 SpMM fused with normalize + weighted sum ----------------
__device__ __forceinline__ float dot4(float4 p) {
    return p.x * p.x + p.y * p.y + p.z * p.z + p.w * p.w;
}

__global__ void __launch_bounds__(256) spmm_final_kernel(
    const float* __restrict__ x2in, const float* __restrict__ emb,
    const float* __restrict__ a, float* __restrict__ out) {
    const int r = (blockIdx.x * blockDim.x + threadIdx.x) >> 5;
    if (r >= N_NODES) return;
    const int lane = threadIdx.x & 31;

    float4 v3 = spmm_row(x2in, r, lane);   // layer 3 row, in registers

    const float4 zero = make_float4(0.f, 0.f, 0.f, 0.f);
    float4 v0 = zero, v1 = zero, v2 = zero;
    if (lane < NF4) {
        v0 = __ldg((const float4*)(emb  + (size_t)r * EMB) + lane);
        v1 = __ldg((const float4*)(g_x1 + (size_t)r * EMB) + lane);
        v2 = __ldg((const float4*)(g_x2 + (size_t)r * EMB) + lane);
    }

    float sq[4];
    sq[0] = dot4(v0); sq[1] = dot4(v1); sq[2] = dot4(v2);
    sq[3] = (lane < NF4) ? dot4(v3) : 0.0f;

    #pragma unroll
    for (int off = 16; off > 0; off >>= 1) {
        #pragma unroll
        for (int l = 0; l < 4; l++)
            sq[l] += __shfl_xor_sync(0xFFFFFFFFu, sq[l], off);
    }

    if (lane < NF4) {
        float w0 = __ldg(&a[0]) / fmaxf(sqrtf(sq[0]), 1e-12f);
        float w1 = __ldg(&a[1]) / fmaxf(sqrtf(sq[1]), 1e-12f);
        float w2 = __ldg(&a[2]) / fmaxf(sqrtf(sq[2]), 1e-12f);
        float w3 = __ldg(&a[3]) / fmaxf(sqrtf(sq[3]), 1e-12f);
        float4 res;
        res.x = w0 * v0.x + w1 * v1.x + w2 * v2.x + w3 * v3.x;
        res.y = w0 * v0.y + w1 * v1.y + w2 * v2.y + w3 * v3.y;
        res.z = w0 * v0.z + w1 * v1.z + w2 * v2.z + w3 * v3.z;
        res.w = w0 * v0.w + w1 * v1.w + w2 * v2.w + w3 * v3.w;
        ((float4*)(out + (size_t)r * EMB))[lane] = res;
    }
}

extern "C" void kernel_launch(void* const* d_in, const int* in_sizes, int n_in,
                              void* d_out, int out_size) {
    const int*   adj_row = (const int*)d_in[0];
    const int*   adj_col = (const int*)d_in[1];
    const float* adj_val = (const float*)d_in[2];
    const float* emb     = (const float*)d_in[3];
    const float* a       = (const float*)d_in[4];
    float*       out     = (float*)d_out;

    float* x1;  cudaGetSymbolAddress((void**)&x1, g_x1);
    float* x2;  cudaGetSymbolAddress((void**)&x2, g_x2);
    int*   cur; cudaGetSymbolAddress((void**)&cur, g_cursor);

    // CSR build (multi-block coalesced scan — single-block chunked scan was a
    // 45us regression in R3)
    cudaMemsetAsync(cur, 0, N_NODES * sizeof(int), 0);
    hist_kernel<<<(N_EDGES + 255) / 256, 256>>>(adj_row);
    block_scan_kernel<<<SCAN_NB, SCAN_B>>>();
    bsum_scan_kernel<<<1, SCAN_B>>>();
    fixup_kernel<<<SCAN_NB, SCAN_B>>>();
    scatter_kernel<<<(N_EDGES + 255) / 256, 256>>>(adj_row, adj_col, adj_val);

    // SpMM layers (warp per row); layer 3 fused with normalize+sum
    const int SPMM_BLOCKS = (N_NODES * 32 + 255) / 256;
    spmm_kernel<<<SPMM_BLOCKS, 256>>>(emb, x1);
    spmm_kernel<<<SPMM_BLOCKS, 256>>>(x1,  x2);
    spmm_final_kernel<<<SPMM_BLOCKS, 256>>>(x2, emb, a, out);
}